// round 8
// baseline (speedup 1.0000x reference)
#include <cuda_runtime.h>
#include <cuda_bf16.h>
#include <cstdint>

#define NUM_NODES 100000
#define EMBED_DIM 64
#define NUM_EDGES 3200000
#define NUM_LAYERS 3

#define SCAN_BS 1024
#define SCAN_NB ((NUM_NODES + SCAN_BS - 1) / SCAN_BS)   // 98

// ---------------- scratch (device globals; no runtime allocation) ----------------
__device__ int   g_is64;                 // 1 if edge_index really is int64
__device__ int   g_deg[NUM_NODES];
__device__ float g_dinv[NUM_NODES];
__device__ int   g_rowptr[NUM_NODES + 1];
__device__ int   g_cursor[NUM_NODES];
__device__ int   g_bsum[SCAN_NB];
__device__ int   g_boff[SCAN_NB];
__device__ int   g_csr_src[NUM_EDGES];
__device__ float g_csr_w[NUM_EDGES];
__device__ float g_x0[(size_t)NUM_NODES * EMBED_DIM];
__device__ float g_x1[(size_t)NUM_NODES * EMBED_DIM];

// ---------------- helpers ----------------

// Fetch edge endpoint `e` of row `row` (0=src, 1=dst), honoring detected dtype.
// Returns -1 if out of range (defensive: never crash, surface as rel_err).
__device__ __forceinline__ int load_idx(const void* ei, int row, int e) {
    long long v;
    if (g_is64) {
        v = ((const long long*)ei)[(size_t)row * NUM_EDGES + e];
    } else {
        v = ((const int*)ei)[(size_t)row * NUM_EDGES + e];
    }
    if ((unsigned long long)v >= (unsigned long long)NUM_NODES) return -1;
    return (int)v;
}

// ---------------- kernels ----------------

// Detect dtype: if the buffer is int64 (values < 1e5), every 8-byte word has a
// zero high half. Random int32 pairs would make the "high half" a full random
// index (zero w.p. ~deg(0)/E per slot) -> 256 consecutive zeros is conclusive.
__global__ void k_detect(const void* ei) {
    if (threadIdx.x == 0 && blockIdx.x == 0) {
        const unsigned long long* p = (const unsigned long long*)ei;
        int all_hi_zero = 1;
        for (int i = 0; i < 256; i++) {
            if ((p[i] >> 32) != 0ull) { all_hi_zero = 0; break; }
        }
        g_is64 = all_hi_zero;
    }
}

__global__ void k_zero_deg() {
    int i = blockIdx.x * blockDim.x + threadIdx.x;
    if (i < NUM_NODES) g_deg[i] = 0;
}

__global__ void k_hist(const void* __restrict__ ei) {
    int e = blockIdx.x * blockDim.x + threadIdx.x;
    if (e < NUM_EDGES) {
        int d = load_idx(ei, 1, e);
        if (d >= 0) atomicAdd(&g_deg[d], 1);
    }
}

__global__ void k_dinv() {
    int i = blockIdx.x * blockDim.x + threadIdx.x;
    if (i < NUM_NODES) {
        int d = g_deg[i];
        g_dinv[i] = (d > 0) ? rsqrtf((float)d) : 0.0f;
    }
}

// scan phase 1: per-block sums of deg
__global__ void k_block_sums() {
    __shared__ int sh[SCAN_BS];
    int tid = threadIdx.x;
    int i = blockIdx.x * SCAN_BS + tid;
    sh[tid] = (i < NUM_NODES) ? g_deg[i] : 0;
    __syncthreads();
    for (int off = SCAN_BS / 2; off > 0; off >>= 1) {
        if (tid < off) sh[tid] += sh[tid + off];
        __syncthreads();
    }
    if (tid == 0) g_bsum[blockIdx.x] = sh[0];
}

// scan phase 2: exclusive scan of block sums (tiny, serial)
__global__ void k_scan_bsums() {
    if (threadIdx.x == 0 && blockIdx.x == 0) {
        int acc = 0;
        for (int b = 0; b < SCAN_NB; b++) {
            int t = g_bsum[b];
            g_boff[b] = acc;
            acc += t;
        }
        g_rowptr[NUM_NODES] = acc;
    }
}

// scan phase 3: per-block exclusive scan + base offset -> rowptr & cursor
__global__ void k_scan_blocks() {
    __shared__ int sh[SCAN_BS];
    int tid = threadIdx.x;
    int i = blockIdx.x * SCAN_BS + tid;
    int v = (i < NUM_NODES) ? g_deg[i] : 0;
    sh[tid] = v;
    __syncthreads();
    // Hillis-Steele inclusive scan
    for (int off = 1; off < SCAN_BS; off <<= 1) {
        int t = (tid >= off) ? sh[tid - off] : 0;
        __syncthreads();
        sh[tid] += t;
        __syncthreads();
    }
    if (i < NUM_NODES) {
        int excl = sh[tid] - v + g_boff[blockIdx.x];
        g_rowptr[i] = excl;
        g_cursor[i] = excl;
    }
}

__global__ void k_scatter(const void* __restrict__ ei) {
    int e = blockIdx.x * blockDim.x + threadIdx.x;
    if (e < NUM_EDGES) {
        int s = load_idx(ei, 0, e);
        int d = load_idx(ei, 1, e);
        if (s >= 0 && d >= 0) {
            int pos = atomicAdd(&g_cursor[d], 1);
            if ((unsigned)pos < (unsigned)NUM_EDGES) {
                g_csr_src[pos] = s;
                g_csr_w[pos]   = g_dinv[s] * g_dinv[d];
            }
        }
    }
}

// SpMM: one warp per dst row; lane owns float2 (cols 2*lane, 2*lane+1).
// Buffer selection in device code from `layer` (graph-capture safe):
//   layer 0: x_in = emb,  x_out = g_x0, out  = 0.25*(emb + acc)
//   layer 1: x_in = g_x0, x_out = g_x1, out += 0.25*acc
//   layer 2: x_in = g_x1, x_out = g_x0, out += 0.25*acc
__global__ void k_spmm(const float* __restrict__ emb,
                       float* __restrict__ out,
                       int layer) {
    int warps_per_block = blockDim.x >> 5;
    int row = blockIdx.x * warps_per_block + (threadIdx.x >> 5);
    if (row >= NUM_NODES) return;
    int lane = threadIdx.x & 31;

    const float* x_in  = (layer == 0) ? emb : ((layer == 1) ? g_x0 : g_x1);
    float*       x_out = (layer == 1) ? g_x1 : g_x0;

    int beg = g_rowptr[row];
    int end = g_rowptr[row + 1];

    float2 acc = make_float2(0.0f, 0.0f);
    for (int b = beg; b < end; b += 32) {
        int n = end - b;
        if (n > 32) n = 32;
        int s = 0;
        float w = 0.0f;
        if (lane < n) {
            s = g_csr_src[b + lane];
            w = g_csr_w[b + lane];
        }
        #pragma unroll 4
        for (int j = 0; j < n; ++j) {
            int   sj = __shfl_sync(0xffffffffu, s, j);
            float wj = __shfl_sync(0xffffffffu, w, j);
            const float2* xr = (const float2*)(x_in + (size_t)sj * EMBED_DIM);
            float2 v = xr[lane];
            acc.x = fmaf(wj, v.x, acc.x);
            acc.y = fmaf(wj, v.y, acc.y);
        }
    }

    float2* xo = (float2*)(x_out + (size_t)row * EMBED_DIM);
    xo[lane] = acc;

    float2* op = (float2*)(out + (size_t)row * EMBED_DIM);
    const float inv = 1.0f / (NUM_LAYERS + 1);
    if (layer == 0) {
        const float2* ep = (const float2*)(emb + (size_t)row * EMBED_DIM);
        float2 ev = ep[lane];
        op[lane] = make_float2(inv * (ev.x + acc.x), inv * (ev.y + acc.y));
    } else {
        float2 prev = op[lane];
        op[lane] = make_float2(prev.x + inv * acc.x, prev.y + inv * acc.y);
    }
}

// ---------------- launch ----------------

extern "C" void kernel_launch(void* const* d_in, const int* in_sizes, int n_in,
                              void* d_out, int out_size) {
    const float* emb = (const float*)d_in[0];
    const void*  ei  = d_in[1];          // int32 or int64 — detected on device
    float*       out = (float*)d_out;

    const int TB = 256;
    const int node_blocks = (NUM_NODES + TB - 1) / TB;
    const int edge_blocks = (NUM_EDGES + TB - 1) / TB;

    // dtype detection + degree/normalization
    k_detect<<<1, 32>>>(ei);
    k_zero_deg<<<node_blocks, TB>>>();
    k_hist<<<edge_blocks, TB>>>(ei);
    k_dinv<<<node_blocks, TB>>>();

    // prefix scan -> rowptr, cursor
    k_block_sums<<<SCAN_NB, SCAN_BS>>>();
    k_scan_bsums<<<1, 32>>>();
    k_scan_blocks<<<SCAN_NB, SCAN_BS>>>();

    // scatter edges into CSR (by dst) with precomputed weights
    k_scatter<<<edge_blocks, TB>>>(ei);

    // 3 propagation layers, fused output accumulation
    const int WPB = TB / 32;                                   // 8 warps/block
    const int spmm_blocks = (NUM_NODES + WPB - 1) / WPB;       // 12500

    k_spmm<<<spmm_blocks, TB>>>(emb, out, 0);
    k_spmm<<<spmm_blocks, TB>>>(emb, out, 1);
    k_spmm<<<spmm_blocks, TB>>>(emb, out, 2);
}

// round 10
// speedup vs baseline: 1.1964x; 1.1964x over previous
#include <cuda_runtime.h>
#include <cuda_fp16.h>
#include <cuda_bf16.h>
#include <cstdint>

#define NUM_NODES 100000
#define EMBED_DIM 64
#define NUM_EDGES 3200000
#define NUM_LAYERS 3

#define SCAN_BS 1024
#define SCAN_NB ((NUM_NODES + SCAN_BS - 1) / SCAN_BS)   // 98

// ---------------- scratch (device globals; no runtime allocation) ----------------
__device__ int    g_is64;                // 1 if edge_index really is int64
__device__ int    g_deg[NUM_NODES];
__device__ float  g_dinv[NUM_NODES];
__device__ int    g_rowptr[NUM_NODES + 1];
__device__ int    g_cursor[NUM_NODES];
__device__ int    g_bsum[SCAN_NB];
__device__ int    g_boff[SCAN_NB];
__device__ int    g_csr_src[NUM_EDGES];
// fp16 ping-pong propagation state: y = dinv * x, stored as half2 pairs
__device__ __half2 g_y0[(size_t)NUM_NODES * (EMBED_DIM / 2)];
__device__ __half2 g_y1[(size_t)NUM_NODES * (EMBED_DIM / 2)];

// ---------------- helpers ----------------

// Fetch edge endpoint `e` of row `row` (0=src, 1=dst), honoring detected dtype.
// Returns -1 if out of range (defensive: surface as rel_err, never crash).
__device__ __forceinline__ int load_idx(const void* ei, int row, int e) {
    long long v;
    if (g_is64) {
        v = ((const long long*)ei)[(size_t)row * NUM_EDGES + e];
    } else {
        v = ((const int*)ei)[(size_t)row * NUM_EDGES + e];
    }
    if ((unsigned long long)v >= (unsigned long long)NUM_NODES) return -1;
    return (int)v;
}

// ---------------- kernels ----------------

// Detect dtype: int64 indices < 1e5 have zero high halves; random int32 pairs don't.
__global__ void k_detect(const void* ei) {
    if (threadIdx.x == 0 && blockIdx.x == 0) {
        const unsigned long long* p = (const unsigned long long*)ei;
        int all_hi_zero = 1;
        for (int i = 0; i < 256; i++) {
            if ((p[i] >> 32) != 0ull) { all_hi_zero = 0; break; }
        }
        g_is64 = all_hi_zero;
    }
}

__global__ void k_zero_deg() {
    int i = blockIdx.x * blockDim.x + threadIdx.x;
    if (i < NUM_NODES) g_deg[i] = 0;
}

__global__ void k_hist(const void* __restrict__ ei) {
    int e = blockIdx.x * blockDim.x + threadIdx.x;
    if (e < NUM_EDGES) {
        int d = load_idx(ei, 1, e);
        if (d >= 0) atomicAdd(&g_deg[d], 1);
    }
}

__global__ void k_dinv() {
    int i = blockIdx.x * blockDim.x + threadIdx.x;
    if (i < NUM_NODES) {
        int d = g_deg[i];
        g_dinv[i] = (d > 0) ? rsqrtf((float)d) : 0.0f;
    }
}

// scan phase 1: per-block sums of deg
__global__ void k_block_sums() {
    __shared__ int sh[SCAN_BS];
    int tid = threadIdx.x;
    int i = blockIdx.x * SCAN_BS + tid;
    sh[tid] = (i < NUM_NODES) ? g_deg[i] : 0;
    __syncthreads();
    for (int off = SCAN_BS / 2; off > 0; off >>= 1) {
        if (tid < off) sh[tid] += sh[tid + off];
        __syncthreads();
    }
    if (tid == 0) g_bsum[blockIdx.x] = sh[0];
}

// scan phase 2: exclusive scan of block sums (tiny, serial)
__global__ void k_scan_bsums() {
    if (threadIdx.x == 0 && blockIdx.x == 0) {
        int acc = 0;
        for (int b = 0; b < SCAN_NB; b++) {
            int t = g_bsum[b];
            g_boff[b] = acc;
            acc += t;
        }
        g_rowptr[NUM_NODES] = acc;
    }
}

// scan phase 3: per-block exclusive scan + base offset -> rowptr & cursor
__global__ void k_scan_blocks() {
    __shared__ int sh[SCAN_BS];
    int tid = threadIdx.x;
    int i = blockIdx.x * SCAN_BS + tid;
    int v = (i < NUM_NODES) ? g_deg[i] : 0;
    sh[tid] = v;
    __syncthreads();
    for (int off = 1; off < SCAN_BS; off <<= 1) {
        int t = (tid >= off) ? sh[tid - off] : 0;
        __syncthreads();
        sh[tid] += t;
        __syncthreads();
    }
    if (i < NUM_NODES) {
        int excl = sh[tid] - v + g_boff[blockIdx.x];
        g_rowptr[i] = excl;
        g_cursor[i] = excl;
    }
}

// Scatter edges into dst-sorted CSR. Separable normalization means we only
// need the src index per edge — no per-edge weight array.
__global__ void k_scatter(const void* __restrict__ ei) {
    int e = blockIdx.x * blockDim.x + threadIdx.x;
    if (e < NUM_EDGES) {
        int s = load_idx(ei, 0, e);
        int d = load_idx(ei, 1, e);
        if (s >= 0 && d >= 0) {
            int pos = atomicAdd(&g_cursor[d], 1);
            if ((unsigned)pos < (unsigned)NUM_EDGES) g_csr_src[pos] = s;
        }
    }
}

// Pre-scale layer-0 state: y0 = dinv[node] * emb, stored fp16.
// One thread per half2 (2 floats).
__global__ void k_prescale(const float* __restrict__ emb) {
    int idx = blockIdx.x * blockDim.x + threadIdx.x;       // over N * 32
    if (idx < NUM_NODES * (EMBED_DIM / 2)) {
        int node = idx >> 5;                                // /32
        float s = g_dinv[node];
        float2 v = ((const float2*)emb)[idx];
        g_y0[idx] = __floats2half2_rn(s * v.x, s * v.y);
    }
}

// SpMM with separable normalization:
//   acc[d]    = Σ_{e: dst=d} y[src(e)]            (plain adds, no weights)
//   x_next[d] = dinv[d] * acc                     -> out += x_next / 4
//   y_next[d] = dinv[d]^2 * acc                   (pre-scaled for next layer)
// One warp per dst row; lane owns a half2 (cols 2*lane, 2*lane+1), fp32 accum.
//   layer 0: y_in = g_y0, y_out = g_y1, out  = 0.25*(emb + dinv*acc)
//   layer 1: y_in = g_y1, y_out = g_y0, out += 0.25*dinv*acc
//   layer 2: y_in = g_y0, no y_out,     out += 0.25*dinv*acc
__global__ void k_spmm(const float* __restrict__ emb,
                       float* __restrict__ out,
                       int layer) {
    int warps_per_block = blockDim.x >> 5;
    int row = blockIdx.x * warps_per_block + (threadIdx.x >> 5);
    if (row >= NUM_NODES) return;
    int lane = threadIdx.x & 31;

    const __half2* y_in  = (layer == 1) ? g_y1 : g_y0;
    __half2*       y_out = (layer == 0) ? g_y1 : g_y0;

    int beg = g_rowptr[row];
    int end = g_rowptr[row + 1];

    float2 acc = make_float2(0.0f, 0.0f);
    for (int b = beg; b < end; b += 32) {
        int n = end - b;
        if (n > 32) n = 32;
        int s = 0;
        if (lane < n) s = g_csr_src[b + lane];
        #pragma unroll 8
        for (int j = 0; j < n; ++j) {
            int sj = __shfl_sync(0xffffffffu, s, j);
            __half2 h = y_in[(size_t)sj * (EMBED_DIM / 2) + lane];
            float2 v = __half22float2(h);
            acc.x += v.x;
            acc.y += v.y;
        }
    }

    float di = g_dinv[row];
    float xn_x = di * acc.x;         // x_next
    float xn_y = di * acc.y;

    if (layer != 2) {                // last layer's y is never read
        y_out[(size_t)row * (EMBED_DIM / 2) + lane] =
            __floats2half2_rn(di * xn_x, di * xn_y);
    }

    float2* op = (float2*)(out + (size_t)row * EMBED_DIM);
    const float inv = 1.0f / (NUM_LAYERS + 1);
    if (layer == 0) {
        const float2* ep = (const float2*)(emb + (size_t)row * EMBED_DIM);
        float2 ev = ep[lane];
        op[lane] = make_float2(inv * (ev.x + xn_x), inv * (ev.y + xn_y));
    } else {
        float2 prev = op[lane];
        op[lane] = make_float2(prev.x + inv * xn_x, prev.y + inv * xn_y);
    }
}

// ---------------- launch ----------------

extern "C" void kernel_launch(void* const* d_in, const int* in_sizes, int n_in,
                              void* d_out, int out_size) {
    const float* emb = (const float*)d_in[0];
    const void*  ei  = d_in[1];          // int32 or int64 — detected on device
    float*       out = (float*)d_out;

    const int TB = 256;
    const int node_blocks = (NUM_NODES + TB - 1) / TB;
    const int edge_blocks = (NUM_EDGES + TB - 1) / TB;

    // dtype detection + degree/normalization
    k_detect<<<1, 32>>>(ei);
    k_zero_deg<<<node_blocks, TB>>>();
    k_hist<<<edge_blocks, TB>>>(ei);
    k_dinv<<<node_blocks, TB>>>();

    // prefix scan -> rowptr, cursor
    k_block_sums<<<SCAN_NB, SCAN_BS>>>();
    k_scan_bsums<<<1, 32>>>();
    k_scan_blocks<<<SCAN_NB, SCAN_BS>>>();

    // scatter edges into CSR (src only)
    k_scatter<<<edge_blocks, TB>>>(ei);

    // pre-scaled fp16 layer-0 state
    const int pre_elems = NUM_NODES * (EMBED_DIM / 2);
    k_prescale<<<(pre_elems + TB - 1) / TB, TB>>>(emb);

    // 3 propagation layers, fused output accumulation
    const int WPB = TB / 32;                                   // 8 warps/block
    const int spmm_blocks = (NUM_NODES + WPB - 1) / WPB;       // 12500

    k_spmm<<<spmm_blocks, TB>>>(emb, out, 0);
    k_spmm<<<spmm_blocks, TB>>>(emb, out, 1);
    k_spmm<<<spmm_blocks, TB>>>(emb, out, 2);
}

// round 11
// speedup vs baseline: 1.3006x; 1.0871x over previous
#include <cuda_runtime.h>
#include <cuda_fp16.h>
#include <cuda_bf16.h>
#include <cstdint>

#define NUM_NODES 100000
#define EMBED_DIM 64
#define NUM_EDGES 3200000
#define NUM_LAYERS 3

#define SCAN_BS 1024
#define SCAN_NB ((NUM_NODES + SCAN_BS - 1) / SCAN_BS)   // 98

// ---------------- scratch (device globals; no runtime allocation) ----------------
__device__ int    g_is64;                // 1 if edge_index really is int64
__device__ int    g_deg[NUM_NODES];
__device__ float  g_dinv[NUM_NODES];
__device__ int    g_rowptr[NUM_NODES + 1];
__device__ int    g_cursor[NUM_NODES];
__device__ int    g_bsum[SCAN_NB];
__device__ int    g_boff[SCAN_NB];
__device__ int    g_csr_src[NUM_EDGES];
// fp16 ping-pong propagation state: y = dinv * x, stored as half2 pairs
__device__ __half2 g_y0[(size_t)NUM_NODES * (EMBED_DIM / 2)];
__device__ __half2 g_y1[(size_t)NUM_NODES * (EMBED_DIM / 2)];

// ---------------- helpers ----------------

// Fetch edge endpoint `e` of row `row` (0=src, 1=dst), honoring detected dtype.
// Returns -1 if out of range (defensive: surface as rel_err, never crash).
__device__ __forceinline__ int load_idx(const void* ei, int row, int e) {
    long long v;
    if (g_is64) {
        v = ((const long long*)ei)[(size_t)row * NUM_EDGES + e];
    } else {
        v = ((const int*)ei)[(size_t)row * NUM_EDGES + e];
    }
    if ((unsigned long long)v >= (unsigned long long)NUM_NODES) return -1;
    return (int)v;
}

// ---------------- kernels ----------------

// Fused: dtype detect (block 0 / thread 0) + zero the degree array (all threads).
__global__ void k_init(const void* ei) {
    int i = blockIdx.x * blockDim.x + threadIdx.x;
    if (i == 0) {
        const unsigned long long* p = (const unsigned long long*)ei;
        int all_hi_zero = 1;
        for (int k = 0; k < 256; k++) {
            if ((p[k] >> 32) != 0ull) { all_hi_zero = 0; break; }
        }
        g_is64 = all_hi_zero;
    }
    if (i < NUM_NODES) g_deg[i] = 0;
}

__global__ void k_hist(const void* __restrict__ ei) {
    int e = blockIdx.x * blockDim.x + threadIdx.x;
    if (e < NUM_EDGES) {
        int d = load_idx(ei, 1, e);
        if (d >= 0) atomicAdd(&g_deg[d], 1);
    }
}

// scan phase 1: per-block sums of deg; fused dinv computation (same index space)
__global__ void k_block_sums() {
    __shared__ int sh[SCAN_BS];
    int tid = threadIdx.x;
    int i = blockIdx.x * SCAN_BS + tid;
    int d = (i < NUM_NODES) ? g_deg[i] : 0;
    if (i < NUM_NODES) g_dinv[i] = (d > 0) ? rsqrtf((float)d) : 0.0f;
    sh[tid] = d;
    __syncthreads();
    for (int off = SCAN_BS / 2; off > 0; off >>= 1) {
        if (tid < off) sh[tid] += sh[tid + off];
        __syncthreads();
    }
    if (tid == 0) g_bsum[blockIdx.x] = sh[0];
}

// scan phase 2: exclusive scan of block sums (tiny, serial)
__global__ void k_scan_bsums() {
    if (threadIdx.x == 0 && blockIdx.x == 0) {
        int acc = 0;
        for (int b = 0; b < SCAN_NB; b++) {
            int t = g_bsum[b];
            g_boff[b] = acc;
            acc += t;
        }
        g_rowptr[NUM_NODES] = acc;
    }
}

// scan phase 3: per-block exclusive scan + base offset -> rowptr & cursor
__global__ void k_scan_blocks() {
    __shared__ int sh[SCAN_BS];
    int tid = threadIdx.x;
    int i = blockIdx.x * SCAN_BS + tid;
    int v = (i < NUM_NODES) ? g_deg[i] : 0;
    sh[tid] = v;
    __syncthreads();
    for (int off = 1; off < SCAN_BS; off <<= 1) {
        int t = (tid >= off) ? sh[tid - off] : 0;
        __syncthreads();
        sh[tid] += t;
        __syncthreads();
    }
    if (i < NUM_NODES) {
        int excl = sh[tid] - v + g_boff[blockIdx.x];
        g_rowptr[i] = excl;
        g_cursor[i] = excl;
    }
}

// Fused: CSR scatter (src only) + layer-0 prescale (y0 = dinv*emb as fp16).
// Both are 3.2M-thread index spaces depending only on the scan output, so one
// grid covers both: thread e scatters edge e AND prescales half2-element e.
__global__ void k_scatter_prescale(const void* __restrict__ ei,
                                   const float* __restrict__ emb) {
    int e = blockIdx.x * blockDim.x + threadIdx.x;
    if (e < NUM_EDGES) {
        int s = load_idx(ei, 0, e);
        int d = load_idx(ei, 1, e);
        if (s >= 0 && d >= 0) {
            int pos = atomicAdd(&g_cursor[d], 1);
            if ((unsigned)pos < (unsigned)NUM_EDGES) g_csr_src[pos] = s;
        }
    }
    // prescale: NUM_NODES * 32 = 3.2M half2 elements — same index space
    if (e < NUM_NODES * (EMBED_DIM / 2)) {
        int node = e >> 5;
        float sc = g_dinv[node];
        float2 v = ((const float2*)emb)[e];
        g_y0[e] = __floats2half2_rn(sc * v.x, sc * v.y);
    }
}

// SpMM with separable normalization:
//   acc[d]    = Σ_{e: dst=d} y[src(e)]            (plain adds, no weights)
//   x_next[d] = dinv[d] * acc                     -> out += x_next / 4
//   y_next[d] = dinv[d]^2 * acc                   (pre-scaled for next layer)
// One warp per dst row; lane owns a half2. Full 32-edge batches are fully
// unrolled -> up to 32 LDGs in flight per warp (latency hiding).
//   layer 0: y_in = g_y0, y_out = g_y1, out  = 0.25*(emb + dinv*acc)
//   layer 1: y_in = g_y1, y_out = g_y0, out += 0.25*dinv*acc
//   layer 2: y_in = g_y0, no y_out,     out += 0.25*dinv*acc
__global__ void k_spmm(const float* __restrict__ emb,
                       float* __restrict__ out,
                       int layer) {
    int warps_per_block = blockDim.x >> 5;
    int row = blockIdx.x * warps_per_block + (threadIdx.x >> 5);
    if (row >= NUM_NODES) return;
    int lane = threadIdx.x & 31;

    const __half2* y_in  = (layer == 1) ? g_y1 : g_y0;
    __half2*       y_out = (layer == 0) ? g_y1 : g_y0;

    int beg = g_rowptr[row];
    int end = g_rowptr[row + 1];

    float2 acc = make_float2(0.0f, 0.0f);
    for (int b = beg; b < end; b += 32) {
        int n = end - b;
        if (n >= 32) {
            int s = g_csr_src[b + lane];
            #pragma unroll
            for (int j = 0; j < 32; ++j) {
                int sj = __shfl_sync(0xffffffffu, s, j);
                float2 v = __half22float2(y_in[(size_t)sj * (EMBED_DIM / 2) + lane]);
                acc.x += v.x;
                acc.y += v.y;
            }
        } else {
            int s = (lane < n) ? g_csr_src[b + lane] : 0;
            #pragma unroll 8
            for (int j = 0; j < n; ++j) {
                int sj = __shfl_sync(0xffffffffu, s, j);
                float2 v = __half22float2(y_in[(size_t)sj * (EMBED_DIM / 2) + lane]);
                acc.x += v.x;
                acc.y += v.y;
            }
        }
    }

    float di = g_dinv[row];
    float xn_x = di * acc.x;         // x_next
    float xn_y = di * acc.y;

    if (layer != 2) {                // last layer's y is never read
        y_out[(size_t)row * (EMBED_DIM / 2) + lane] =
            __floats2half2_rn(di * xn_x, di * xn_y);
    }

    float2* op = (float2*)(out + (size_t)row * EMBED_DIM);
    const float inv = 1.0f / (NUM_LAYERS + 1);
    if (layer == 0) {
        const float2* ep = (const float2*)(emb + (size_t)row * EMBED_DIM);
        float2 ev = ep[lane];
        op[lane] = make_float2(inv * (ev.x + xn_x), inv * (ev.y + xn_y));
    } else {
        float2 prev = op[lane];
        op[lane] = make_float2(prev.x + inv * xn_x, prev.y + inv * xn_y);
    }
}

// ---------------- launch ----------------

extern "C" void kernel_launch(void* const* d_in, const int* in_sizes, int n_in,
                              void* d_out, int out_size) {
    const float* emb = (const float*)d_in[0];
    const void*  ei  = d_in[1];          // int32 or int64 — detected on device
    float*       out = (float*)d_out;

    const int TB = 256;
    const int node_blocks = (NUM_NODES + TB - 1) / TB;
    const int edge_blocks = (NUM_EDGES + TB - 1) / TB;

    // detect dtype + zero degrees (fused), then histogram
    k_init<<<node_blocks, TB>>>(ei);
    k_hist<<<edge_blocks, TB>>>(ei);

    // prefix scan (phase 1 also computes dinv) -> rowptr, cursor
    k_block_sums<<<SCAN_NB, SCAN_BS>>>();
    k_scan_bsums<<<1, 32>>>();
    k_scan_blocks<<<SCAN_NB, SCAN_BS>>>();

    // scatter edges into CSR + prescale layer-0 fp16 state (fused)
    k_scatter_prescale<<<edge_blocks, TB>>>(ei, emb);

    // 3 propagation layers, fused output accumulation
    const int WPB = TB / 32;                                   // 8 warps/block
    const int spmm_blocks = (NUM_NODES + WPB - 1) / WPB;       // 12500

    k_spmm<<<spmm_blocks, TB>>>(emb, out, 0);
    k_spmm<<<spmm_blocks, TB>>>(emb, out, 1);
    k_spmm<<<spmm_blocks, TB>>>(emb, out, 2);
}